// round 10
// baseline (speedup 1.0000x reference)
#include <cuda_runtime.h>
#include <cuda_bf16.h>
#include <cstdint>

// Problem constants
#define BB   2
#define SS   2048
#define DD   1024
#define HH   16
#define HD   64
#define MTOT (BB * SS)          // 4096

// ---------------- scratch (no cudaMalloc allowed) ----------------
__device__ __nv_bfloat16 g_xhi[MTOT * DD];
__device__ __nv_bfloat16 g_xlo[MTOT * DD];
__device__ __nv_bfloat16 g_qhi[MTOT * DD];
__device__ __nv_bfloat16 g_qlo[MTOT * DD];
__device__ __nv_bfloat16 g_khi[MTOT * DD];
__device__ __nv_bfloat16 g_klo[MTOT * DD];
__device__ __nv_bfloat16 g_vhi[MTOT * DD];
__device__ __nv_bfloat16 g_vlo[MTOT * DD];
__device__ __nv_bfloat16 g_ahi[MTOT * DD];
__device__ __nv_bfloat16 g_alo[MTOT * DD];
__device__ __nv_bfloat16 g_wqhi[DD * DD];
__device__ __nv_bfloat16 g_wqlo[DD * DD];
__device__ __nv_bfloat16 g_wkhi[DD * DD];
__device__ __nv_bfloat16 g_wklo[DD * DD];
__device__ __nv_bfloat16 g_wvhi[DD * DD];
__device__ __nv_bfloat16 g_wvlo[DD * DD];
__device__ __nv_bfloat16 g_wohi[DD * DD];
__device__ __nv_bfloat16 g_wolo[DD * DD];

// ---------------- helpers ----------------
__device__ __forceinline__ uint32_t smem_u32(const void* p) {
    uint32_t a;
    asm("{ .reg .u64 t; cvta.to.shared.u64 t, %1; cvt.u32.u64 %0, t; }" : "=r"(a) : "l"(p));
    return a;
}
#define CP_ASYNC16(dst, src) \
    asm volatile("cp.async.cg.shared.global [%0], [%1], 16;" :: "r"(dst), "l"(src))
#define CP_COMMIT() asm volatile("cp.async.commit_group;" ::: "memory")
#define CP_WAIT1()  asm volatile("cp.async.wait_group 1;" ::: "memory")
#define CP_WAIT0()  asm volatile("cp.async.wait_group 0;" ::: "memory")

__device__ __forceinline__ void ldsm_x4(uint32_t& r0, uint32_t& r1, uint32_t& r2,
                                        uint32_t& r3, uint32_t addr) {
    asm volatile("ldmatrix.sync.aligned.m8n8.x4.shared.b16 {%0,%1,%2,%3}, [%4];"
                 : "=r"(r0), "=r"(r1), "=r"(r2), "=r"(r3) : "r"(addr));
}
__device__ __forceinline__ void ldsm_x4_t(uint32_t& r0, uint32_t& r1, uint32_t& r2,
                                          uint32_t& r3, uint32_t addr) {
    asm volatile("ldmatrix.sync.aligned.m8n8.x4.trans.shared.b16 {%0,%1,%2,%3}, [%4];"
                 : "=r"(r0), "=r"(r1), "=r"(r2), "=r"(r3) : "r"(addr));
}
__device__ __forceinline__ void mma_bf16(float* d, const uint32_t* a, const uint32_t* b) {
    asm volatile(
        "mma.sync.aligned.m16n8k16.row.col.f32.bf16.bf16.f32 "
        "{%0,%1,%2,%3}, {%4,%5,%6,%7}, {%8,%9}, {%0,%1,%2,%3};"
        : "+f"(d[0]), "+f"(d[1]), "+f"(d[2]), "+f"(d[3])
        : "r"(a[0]), "r"(a[1]), "r"(a[2]), "r"(a[3]), "r"(b[0]), "r"(b[1]));
}

// split x,y (fp32) into packed bf16x2 hi and lo words (elem x in low half)
__device__ __forceinline__ void split_pack(float x, float y, uint32_t& hi, uint32_t& lo) {
    __nv_bfloat16 hx = __float2bfloat16(x);
    __nv_bfloat16 hy = __float2bfloat16(y);
    __nv_bfloat16 lx = __float2bfloat16(x - __bfloat162float(hx));
    __nv_bfloat16 ly = __float2bfloat16(y - __bfloat162float(hy));
    hi = ((uint32_t)__bfloat16_as_ushort(hy) << 16) | (uint32_t)__bfloat16_as_ushort(hx);
    lo = ((uint32_t)__bfloat16_as_ushort(ly) << 16) | (uint32_t)__bfloat16_as_ushort(lx);
}

// ---------------- fp32 -> bf16 hi/lo split kernels ----------------
struct alignas(8) bfq { __nv_bfloat16 a, b, c, d; };

__device__ __forceinline__ void split_one(const float* x, __nv_bfloat16* hi,
                                          __nv_bfloat16* lo, int i) {
    float4 v = *reinterpret_cast<const float4*>(x + i * 4);
    __nv_bfloat16 h0 = __float2bfloat16(v.x);
    __nv_bfloat16 h1 = __float2bfloat16(v.y);
    __nv_bfloat16 h2 = __float2bfloat16(v.z);
    __nv_bfloat16 h3 = __float2bfloat16(v.w);
    bfq hq = {h0, h1, h2, h3};
    bfq lq = {__float2bfloat16(v.x - __bfloat162float(h0)),
              __float2bfloat16(v.y - __bfloat162float(h1)),
              __float2bfloat16(v.z - __bfloat162float(h2)),
              __float2bfloat16(v.w - __bfloat162float(h3))};
    *reinterpret_cast<bfq*>(hi + i * 4) = hq;
    *reinterpret_cast<bfq*>(lo + i * 4) = lq;
}

__global__ __launch_bounds__(256) void split_bf16(
    const float* __restrict__ x, __nv_bfloat16* __restrict__ hi,
    __nv_bfloat16* __restrict__ lo, int n4)
{
    int i = blockIdx.x * blockDim.x + threadIdx.x;
    if (i < n4) split_one(x, hi, lo, i);
}

__global__ __launch_bounds__(256) void split_w4(
    const float* __restrict__ w0, const float* __restrict__ w1,
    const float* __restrict__ w2, const float* __restrict__ w3,
    __nv_bfloat16* __restrict__ h0, __nv_bfloat16* __restrict__ l0,
    __nv_bfloat16* __restrict__ h1, __nv_bfloat16* __restrict__ l1,
    __nv_bfloat16* __restrict__ h2, __nv_bfloat16* __restrict__ l2,
    __nv_bfloat16* __restrict__ h3, __nv_bfloat16* __restrict__ l3)
{
    int w = blockIdx.x >> 10;
    int i = ((blockIdx.x & 1023) << 8) + threadIdx.x;
    const float* x = (w == 0) ? w0 : (w == 1) ? w1 : (w == 2) ? w2 : w3;
    __nv_bfloat16* hi = (w == 0) ? h0 : (w == 1) ? h1 : (w == 2) ? h2 : h3;
    __nv_bfloat16* lo = (w == 0) ? l0 : (w == 1) ? l1 : (w == 2) ? l2 : l3;
    split_one(x, hi, lo, i);
}

// ---------------- HMMA GEMM, bf16x3 split ----------------
#define BK      32
#define LDS_S   40
#define TILE_B  (128 * LDS_S * 2)
#define STAGE_B (4 * TILE_B)
#define GSMEM_TOTAL (2 * STAGE_B)
#define NCHUNK  32

template <int OM>
__global__ __launch_bounds__(256, 2) void gemm3(
    const __nv_bfloat16* __restrict__ Ahi, const __nv_bfloat16* __restrict__ Alo,
    const __nv_bfloat16* __restrict__ W0h, const __nv_bfloat16* __restrict__ W0l,
    const __nv_bfloat16* __restrict__ W1h, const __nv_bfloat16* __restrict__ W1l,
    const __nv_bfloat16* __restrict__ W2h, const __nv_bfloat16* __restrict__ W2l,
    const float* __restrict__ b0, const float* __restrict__ b1, const float* __restrict__ b2,
    float* __restrict__ C0,
    __nv_bfloat16* __restrict__ H0, __nv_bfloat16* __restrict__ L0,
    __nv_bfloat16* __restrict__ H1, __nv_bfloat16* __restrict__ L1,
    __nv_bfloat16* __restrict__ H2, __nv_bfloat16* __restrict__ L2,
    float scale0)
{
    extern __shared__ __align__(16) char smem[];

    const int z = blockIdx.z;
    const __nv_bfloat16* Bh = (z == 0) ? W0h : (z == 1) ? W1h : W2h;
    const __nv_bfloat16* Bl = (z == 0) ? W0l : (z == 1) ? W1l : W2l;
    const float* bias = (z == 0) ? b0 : (z == 1) ? b1 : b2;
    __nv_bfloat16* OH = (z == 0) ? H0 : (z == 1) ? H1 : H2;
    __nv_bfloat16* OL = (z == 0) ? L0 : (z == 1) ? L1 : L2;
    const float scale = (z == 0) ? scale0 : 1.0f;

    const int tid  = threadIdx.x;
    const int wid  = tid >> 5;
    const int lane = tid & 31;
    const int n0   = blockIdx.x * 128;
    const int m0   = blockIdx.y * 128;
    const int wm   = (wid >> 2) * 64;
    const int wn   = (wid & 3) * 32;

    float acc[4][4][4];
#pragma unroll
    for (int i = 0; i < 4; i++)
#pragma unroll
        for (int j = 0; j < 4; j++)
#pragma unroll
            for (int r = 0; r < 4; r++) acc[i][j][r] = 0.f;

    const int ar = (lane & 7) + ((lane >> 3) & 1) * 8;
    const int ac = (lane >> 4) * 8;
    const int br = (lane & 7) + ((lane >> 4) & 1) * 8;
    const int bc = ((lane >> 3) & 1) * 8;

    const uint32_t sbase = smem_u32(smem);
    const int lrow = tid >> 2;
    const int lseg = (tid & 3) * 8;
    auto load_chunk = [&](int c, int s) {
        const int kc = c * BK;
        const uint32_t sb = sbase + s * STAGE_B;
        const __nv_bfloat16* srcs[4] = { Ahi, Alo, Bh, Bl };
        const int rowbase[4] = { m0, m0, n0, n0 };
#pragma unroll
        for (int t4 = 0; t4 < 4; t4++) {
            const __nv_bfloat16* src = srcs[t4];
#pragma unroll
            for (int i = 0; i < 2; i++) {
                int row = lrow + i * 64;
                uint32_t d = sb + t4 * TILE_B + (row * LDS_S + lseg) * 2;
                CP_ASYNC16(d, src + (size_t)(rowbase[t4] + row) * DD + kc + lseg);
            }
        }
        CP_COMMIT();
    };

    load_chunk(0, 0);

    for (int c = 0; c < NCHUNK; c++) {
        const int s = c & 1;
        if (c + 1 < NCHUNK) { load_chunk(c + 1, s ^ 1); CP_WAIT1(); }
        else                { CP_WAIT0(); }
        __syncthreads();

        const uint32_t sb = sbase + s * STAGE_B;
#pragma unroll
        for (int ks = 0; ks < 2; ks++) {
            const int k = ks * 16;
            uint32_t af[4][4];
#pragma unroll
            for (int mi = 0; mi < 4; mi++) {
                uint32_t a = sb + 0 * TILE_B + ((wm + mi * 16 + ar) * LDS_S + k + ac) * 2;
                ldsm_x4(af[mi][0], af[mi][1], af[mi][2], af[mi][3], a);
            }
            uint32_t bfh[4][2];
#pragma unroll
            for (int pr = 0; pr < 2; pr++) {
                uint32_t a = sb + 2 * TILE_B + ((wn + pr * 16 + br) * LDS_S + k + bc) * 2;
                uint32_t r0, r1, r2, r3;
                ldsm_x4(r0, r1, r2, r3, a);
                bfh[pr * 2 + 0][0] = r0; bfh[pr * 2 + 0][1] = r1;
                bfh[pr * 2 + 1][0] = r2; bfh[pr * 2 + 1][1] = r3;
            }
            uint32_t bfl[4][2];
#pragma unroll
            for (int pr = 0; pr < 2; pr++) {
                uint32_t a = sb + 3 * TILE_B + ((wn + pr * 16 + br) * LDS_S + k + bc) * 2;
                uint32_t r0, r1, r2, r3;
                ldsm_x4(r0, r1, r2, r3, a);
                bfl[pr * 2 + 0][0] = r0; bfl[pr * 2 + 0][1] = r1;
                bfl[pr * 2 + 1][0] = r2; bfl[pr * 2 + 1][1] = r3;
            }
#pragma unroll
            for (int mi = 0; mi < 4; mi++)
#pragma unroll
                for (int ni = 0; ni < 4; ni++)
                    mma_bf16(acc[mi][ni], af[mi], bfh[ni]);
#pragma unroll
            for (int mi = 0; mi < 4; mi++)
#pragma unroll
                for (int ni = 0; ni < 4; ni++)
                    mma_bf16(acc[mi][ni], af[mi], bfl[ni]);
#pragma unroll
            for (int mi = 0; mi < 4; mi++) {
                uint32_t a = sb + 1 * TILE_B + ((wm + mi * 16 + ar) * LDS_S + k + ac) * 2;
                ldsm_x4(af[mi][0], af[mi][1], af[mi][2], af[mi][3], a);
            }
#pragma unroll
            for (int mi = 0; mi < 4; mi++)
#pragma unroll
                for (int ni = 0; ni < 4; ni++)
                    mma_bf16(acc[mi][ni], af[mi], bfh[ni]);
        }
        __syncthreads();
    }

    const int t4 = lane >> 2;
    const int t2 = (lane & 3) * 2;
#pragma unroll
    for (int mi = 0; mi < 4; mi++) {
#pragma unroll
        for (int half = 0; half < 2; half++) {
            const int row = m0 + wm + mi * 16 + t4 + half * 8;
#pragma unroll
            for (int ni = 0; ni < 4; ni++) {
                const int col = wn + ni * 8 + t2;
                float ox = (acc[mi][ni][half * 2 + 0] + bias[n0 + col + 0]) * scale;
                float oy = (acc[mi][ni][half * 2 + 1] + bias[n0 + col + 1]) * scale;
                if (OM == 0) {
                    float2 o = make_float2(ox, oy);
                    *reinterpret_cast<float2*>(C0 + (size_t)row * DD + n0 + col) = o;
                } else {
                    uint32_t ph, pl;
                    split_pack(ox, oy, ph, pl);
                    *reinterpret_cast<uint32_t*>(OH + (size_t)row * DD + n0 + col) = ph;
                    *reinterpret_cast<uint32_t*>(OL + (size_t)row * DD + n0 + col) = pl;
                }
            }
        }
    }
}

// ---------------- tensor-core causal flash attention ----------------
// CTA: 128 queries, 8 warps (256 thr). Warp w: rows w*16..w*16+15.
// K/V stages: 64 keys. S = Q.K^T 3-pass split; online softmax; O = P.V 3-pass.
#define ATT_STR 72                         // halves per smem row (64 + 8)
#define ATT_TILE  (64 * ATT_STR * 2)       // 9216 B (K/V tile)
#define ATT_TILEQ (128 * ATT_STR * 2)      // 18432 B (Q tile)
#define ATT_SMEM (2 * ATT_TILEQ + 8 * ATT_TILE)   // 110592 B

__global__ __launch_bounds__(256) void attn_tc(
    const __nv_bfloat16* __restrict__ Qh, const __nv_bfloat16* __restrict__ Ql,
    const __nv_bfloat16* __restrict__ Kh, const __nv_bfloat16* __restrict__ Kl,
    const __nv_bfloat16* __restrict__ Vh, const __nv_bfloat16* __restrict__ Vl,
    __nv_bfloat16* __restrict__ Ah, __nv_bfloat16* __restrict__ Al)
{
    extern __shared__ __align__(16) char smem[];
    const int qb = (int)gridDim.x - 1 - (int)blockIdx.x;   // heavy CTAs first
    const int b  = blockIdx.y >> 4;
    const int h  = blockIdx.y & 15;
    const int tid = threadIdx.x, wid = tid >> 5, lane = tid & 31;

    const size_t base = ((size_t)b * SS) * DD + (size_t)h * HD;
    const uint32_t sb = smem_u32(smem);
    const uint32_t sQh = sb, sQl = sb + ATT_TILEQ;
    auto stile = [&](int s, int t) { return sb + 2 * ATT_TILEQ + (s * 4 + t) * ATT_TILE; };

    // K/V tile loader: 64x64 bf16, 256 thr x 2 chunks of 16B
    const int lr = tid >> 3;           // 0..31 -> rows lr, lr+32
    const int lg = (tid & 7) * 8;      // halves
    auto load_tile64 = [&](const __nv_bfloat16* src, int row0, uint32_t dst) {
#pragma unroll
        for (int i = 0; i < 2; i++) {
            int row = lr + i * 32;
            CP_ASYNC16(dst + (row * ATT_STR + lg) * 2,
                       src + base + (size_t)(row0 + row) * DD + lg);
        }
    };
    auto load_stage = [&](int kb, int s) {
        const int r0 = kb * 64;
        load_tile64(Kh, r0, stile(s, 0));
        load_tile64(Kl, r0, stile(s, 1));
        load_tile64(Vh, r0, stile(s, 2));
        load_tile64(Vl, r0, stile(s, 3));
        CP_COMMIT();
    };

    // Q tile: 128x64 x2 (hi,lo), 256 thr x 4 chunks each
    {
        const int q0 = qb * 128;
#pragma unroll
        for (int i = 0; i < 4; i++) {
            int row = lr + i * 32;
            CP_ASYNC16(sQh + (row * ATT_STR + lg) * 2,
                       Qh + base + (size_t)(q0 + row) * DD + lg);
            CP_ASYNC16(sQl + (row * ATT_STR + lg) * 2,
                       Ql + base + (size_t)(q0 + row) * DD + lg);
        }
        CP_COMMIT();
    }
    load_stage(0, 0);
    CP_WAIT1();              // Q arrived
    __syncthreads();

    const int ar = (lane & 7) + ((lane >> 3) & 1) * 8;
    const int ac = (lane >> 4) * 8;
    const int br = (lane & 7) + ((lane >> 4) & 1) * 8;
    const int bc = ((lane >> 3) & 1) * 8;

    // Q frags for this warp's 16 rows
    uint32_t qh[4][4], ql[4][4];
#pragma unroll
    for (int kt = 0; kt < 4; kt++) {
        uint32_t a = ((wid * 16 + ar) * ATT_STR + kt * 16 + ac) * 2;
        ldsm_x4(qh[kt][0], qh[kt][1], qh[kt][2], qh[kt][3], sQh + a);
        ldsm_x4(ql[kt][0], ql[kt][1], ql[kt][2], ql[kt][3], sQl + a);
    }

    float oacc[8][4];
#pragma unroll
    for (int nt = 0; nt < 8; nt++)
#pragma unroll
        for (int j = 0; j < 4; j++) oacc[nt][j] = 0.f;
    float mrow[2] = { -1e30f, -1e30f };
    float lrow[2] = { 0.f, 0.f };

    const int r0l = lane >> 2;
    const int c0l = (lane & 3) * 2;
    const int wrow_max = qb * 128 + wid * 16 + 15;   // last query row this warp owns
    const int nkb = 2 * qb + 2;                      // key blocks to visit

    for (int kb = 0; kb < nkb; kb++) {
        const int s = kb & 1;
        if (kb + 1 < nkb) { load_stage(kb + 1, s ^ 1); CP_WAIT1(); }
        else              { CP_WAIT0(); }
        __syncthreads();

        // whole 64-key block above this warp's diagonal -> all masked -> no-op
        if (kb * 64 <= wrow_max) {
            // ---- scores ----
            float sacc[8][4];
#pragma unroll
            for (int nt = 0; nt < 8; nt++)
#pragma unroll
                for (int j = 0; j < 4; j++) sacc[nt][j] = 0.f;

#pragma unroll
            for (int kt = 0; kt < 4; kt++) {
#pragma unroll
                for (int pr = 0; pr < 4; pr++) {
                    uint32_t addr = ((pr * 16 + br) * ATT_STR + kt * 16 + bc) * 2;
                    uint32_t h0, h1, h2, h3;
                    ldsm_x4(h0, h1, h2, h3, stile(s, 0) + addr);   // K_hi
                    uint32_t bh0[2] = { h0, h1 }, bh1[2] = { h2, h3 };
                    mma_bf16(sacc[pr * 2 + 0], qh[kt], bh0);
                    mma_bf16(sacc[pr * 2 + 1], qh[kt], bh1);
                    mma_bf16(sacc[pr * 2 + 0], ql[kt], bh0);
                    mma_bf16(sacc[pr * 2 + 1], ql[kt], bh1);
                    uint32_t l0, l1, l2, l3;
                    ldsm_x4(l0, l1, l2, l3, stile(s, 1) + addr);   // K_lo
                    uint32_t bl0[2] = { l0, l1 }, bl1[2] = { l2, l3 };
                    mma_bf16(sacc[pr * 2 + 0], qh[kt], bl0);
                    mma_bf16(sacc[pr * 2 + 1], qh[kt], bl1);
                }
            }

            // ---- causal mask (only the last two key blocks can clip) ----
            if (kb >= 2 * qb) {
                const int grow = qb * 128 + wid * 16 + r0l;
                const int gc0 = kb * 64;
#pragma unroll
                for (int nt = 0; nt < 8; nt++) {
                    const int col = gc0 + nt * 8 + c0l;
                    if (col > grow)          sacc[nt][0] = -3.0e38f;
                    if (col + 1 > grow)      sacc[nt][1] = -3.0e38f;
                    if (col > grow + 8)      sacc[nt][2] = -3.0e38f;
                    if (col + 1 > grow + 8)  sacc[nt][3] = -3.0e38f;
                }
            }

            // ---- online softmax ----
            float mx0 = sacc[0][0], mx1 = sacc[0][2];
#pragma unroll
            for (int nt = 0; nt < 8; nt++) {
                mx0 = fmaxf(mx0, fmaxf(sacc[nt][0], sacc[nt][1]));
                mx1 = fmaxf(mx1, fmaxf(sacc[nt][2], sacc[nt][3]));
            }
            mx0 = fmaxf(mx0, __shfl_xor_sync(0xffffffffu, mx0, 1));
            mx0 = fmaxf(mx0, __shfl_xor_sync(0xffffffffu, mx0, 2));
            mx1 = fmaxf(mx1, __shfl_xor_sync(0xffffffffu, mx1, 1));
            mx1 = fmaxf(mx1, __shfl_xor_sync(0xffffffffu, mx1, 2));
            const float mn0 = fmaxf(mrow[0], mx0);
            const float mn1 = fmaxf(mrow[1], mx1);
            const float cr0 = __expf(mrow[0] - mn0);
            const float cr1 = __expf(mrow[1] - mn1);
            mrow[0] = mn0; mrow[1] = mn1;
            lrow[0] *= cr0; lrow[1] *= cr1;
#pragma unroll
            for (int nt = 0; nt < 8; nt++) {
                oacc[nt][0] *= cr0; oacc[nt][1] *= cr0;
                oacc[nt][2] *= cr1; oacc[nt][3] *= cr1;
            }
            float ls0 = 0.f, ls1 = 0.f;
#pragma unroll
            for (int nt = 0; nt < 8; nt++) {
                float p0 = __expf(sacc[nt][0] - mn0);
                float p1 = __expf(sacc[nt][1] - mn0);
                float p2 = __expf(sacc[nt][2] - mn1);
                float p3 = __expf(sacc[nt][3] - mn1);
                ls0 += p0 + p1; ls1 += p2 + p3;
                sacc[nt][0] = p0; sacc[nt][1] = p1;
                sacc[nt][2] = p2; sacc[nt][3] = p3;
            }
            lrow[0] += ls0; lrow[1] += ls1;

            // ---- P frags, split hi/lo ----
            uint32_t phi[4][4], plo[4][4];
#pragma unroll
            for (int kt = 0; kt < 4; kt++) {
                split_pack(sacc[2 * kt][0],     sacc[2 * kt][1],     phi[kt][0], plo[kt][0]);
                split_pack(sacc[2 * kt][2],     sacc[2 * kt][3],     phi[kt][1], plo[kt][1]);
                split_pack(sacc[2 * kt + 1][0], sacc[2 * kt + 1][1], phi[kt][2], plo[kt][2]);
                split_pack(sacc[2 * kt + 1][2], sacc[2 * kt + 1][3], phi[kt][3], plo[kt][3]);
            }

            // ---- O += P.V (V via ldmatrix.trans) ----
#pragma unroll
            for (int kt = 0; kt < 4; kt++) {
#pragma unroll
                for (int pn = 0; pn < 4; pn++) {
                    uint32_t addr = ((kt * 16 + (lane & 15)) * ATT_STR
                                     + pn * 16 + ((lane >> 4) << 3)) * 2;
                    uint32_t h0, h1, h2, h3;
                    ldsm_x4_t(h0, h1, h2, h3, stile(s, 2) + addr);   // V_hi
                    uint32_t vh0[2] = { h0, h1 }, vh1[2] = { h2, h3 };
                    mma_bf16(oacc[pn * 2 + 0], phi[kt], vh0);
                    mma_bf16(oacc[pn * 2 + 1], phi[kt], vh1);
                    mma_bf16(oacc[pn * 2 + 0], plo[kt], vh0);
                    mma_bf16(oacc[pn * 2 + 1], plo[kt], vh1);
                    uint32_t l0, l1, l2, l3;
                    ldsm_x4_t(l0, l1, l2, l3, stile(s, 3) + addr);   // V_lo
                    uint32_t vl0[2] = { l0, l1 }, vl1[2] = { l2, l3 };
                    mma_bf16(oacc[pn * 2 + 0], phi[kt], vl0);
                    mma_bf16(oacc[pn * 2 + 1], phi[kt], vl1);
                }
            }
        }
        __syncthreads();
    }

    // finalize
    float lt0 = lrow[0], lt1 = lrow[1];
    lt0 += __shfl_xor_sync(0xffffffffu, lt0, 1);
    lt0 += __shfl_xor_sync(0xffffffffu, lt0, 2);
    lt1 += __shfl_xor_sync(0xffffffffu, lt1, 1);
    lt1 += __shfl_xor_sync(0xffffffffu, lt1, 2);
    const float inv0 = 1.f / lt0;
    const float inv1 = 1.f / lt1;

    const int rg0 = b * SS + qb * 128 + wid * 16 + r0l;
    const int rg1 = rg0 + 8;
#pragma unroll
    for (int nt = 0; nt < 8; nt++) {
        const int col = h * HD + nt * 8 + c0l;
        uint32_t ph, pl;
        split_pack(oacc[nt][0] * inv0, oacc[nt][1] * inv0, ph, pl);
        *reinterpret_cast<uint32_t*>(Ah + (size_t)rg0 * DD + col) = ph;
        *reinterpret_cast<uint32_t*>(Al + (size_t)rg0 * DD + col) = pl;
        split_pack(oacc[nt][2] * inv1, oacc[nt][3] * inv1, ph, pl);
        *reinterpret_cast<uint32_t*>(Ah + (size_t)rg1 * DD + col) = ph;
        *reinterpret_cast<uint32_t*>(Al + (size_t)rg1 * DD + col) = pl;
    }
}

// ---------------------------------------------------------------------------
extern "C" void kernel_launch(void* const* d_in, const int* in_sizes, int n_in,
                              void* d_out, int out_size)
{
    const float* X  = (const float*)d_in[0];
    const float* Wq = (const float*)d_in[2];
    const float* bq = (const float*)d_in[3];
    const float* Wk = (const float*)d_in[4];
    const float* bk = (const float*)d_in[5];
    const float* Wv = (const float*)d_in[6];
    const float* bv = (const float*)d_in[7];
    const float* Wo = (const float*)d_in[8];
    const float* bo = (const float*)d_in[9];
    float* out = (float*)d_out;

    __nv_bfloat16 *xhi, *xlo, *qhi, *qlo, *khi, *klo, *vhi, *vlo, *ahi, *alo;
    __nv_bfloat16 *wqhi, *wqlo, *wkhi, *wklo, *wvhi, *wvlo, *wohi, *wolo;
    cudaGetSymbolAddress((void**)&xhi,  g_xhi);  cudaGetSymbolAddress((void**)&xlo,  g_xlo);
    cudaGetSymbolAddress((void**)&qhi,  g_qhi);  cudaGetSymbolAddress((void**)&qlo,  g_qlo);
    cudaGetSymbolAddress((void**)&khi,  g_khi);  cudaGetSymbolAddress((void**)&klo,  g_klo);
    cudaGetSymbolAddress((void**)&vhi,  g_vhi);  cudaGetSymbolAddress((void**)&vlo,  g_vlo);
    cudaGetSymbolAddress((void**)&ahi,  g_ahi);  cudaGetSymbolAddress((void**)&alo,  g_alo);
    cudaGetSymbolAddress((void**)&wqhi, g_wqhi); cudaGetSymbolAddress((void**)&wqlo, g_wqlo);
    cudaGetSymbolAddress((void**)&wkhi, g_wkhi); cudaGetSymbolAddress((void**)&wklo, g_wklo);
    cudaGetSymbolAddress((void**)&wvhi, g_wvhi); cudaGetSymbolAddress((void**)&wvlo, g_wvlo);
    cudaGetSymbolAddress((void**)&wohi, g_wohi); cudaGetSymbolAddress((void**)&wolo, g_wolo);

    cudaFuncSetAttribute(gemm3<0>, cudaFuncAttributeMaxDynamicSharedMemorySize, GSMEM_TOTAL);
    cudaFuncSetAttribute(gemm3<1>, cudaFuncAttributeMaxDynamicSharedMemorySize, GSMEM_TOTAL);
    cudaFuncSetAttribute(attn_tc,  cudaFuncAttributeMaxDynamicSharedMemorySize, ATT_SMEM);

    const int nX4 = MTOT * DD / 4;

    split_bf16<<<nX4 / 256, 256>>>(X, xhi, xlo, nX4);
    split_w4<<<4096, 256>>>(Wq, Wk, Wv, Wo,
                            wqhi, wqlo, wkhi, wklo, wvhi, wvlo, wohi, wolo);

    const dim3 ggrid(DD / 128, MTOT / 128, 3);
    gemm3<1><<<ggrid, 256, GSMEM_TOTAL>>>(xhi, xlo,
                                          wqhi, wqlo, wkhi, wklo, wvhi, wvlo,
                                          bq, bk, bv, nullptr,
                                          qhi, qlo, khi, klo, vhi, vlo, 0.125f);

    attn_tc<<<dim3(SS / 128, BB * HH), 256, ATT_SMEM>>>(qhi, qlo, khi, klo,
                                                        vhi, vlo, ahi, alo);

    const dim3 ogrid(DD / 128, MTOT / 128, 1);
    gemm3<0><<<ogrid, 256, GSMEM_TOTAL>>>(ahi, alo,
                                          wohi, wolo, wohi, wolo, wohi, wolo,
                                          bo, bo, bo, out,
                                          nullptr, nullptr, nullptr, nullptr,
                                          nullptr, nullptr, 1.0f);
}

// round 11
// speedup vs baseline: 1.0695x; 1.0695x over previous
#include <cuda_runtime.h>
#include <cuda_bf16.h>
#include <cstdint>

// Problem constants
#define BB   2
#define SS   2048
#define DD   1024
#define HH   16
#define HD   64
#define MTOT (BB * SS)          // 4096

// ---------------- scratch (no cudaMalloc allowed) ----------------
__device__ __nv_bfloat16 g_xhi[MTOT * DD];
__device__ __nv_bfloat16 g_xlo[MTOT * DD];
__device__ __nv_bfloat16 g_qhi[MTOT * DD];
__device__ __nv_bfloat16 g_qlo[MTOT * DD];
__device__ __nv_bfloat16 g_khi[MTOT * DD];
__device__ __nv_bfloat16 g_klo[MTOT * DD];
__device__ __nv_bfloat16 g_vhi[MTOT * DD];
__device__ __nv_bfloat16 g_vlo[MTOT * DD];
__device__ __nv_bfloat16 g_ahi[MTOT * DD];
__device__ __nv_bfloat16 g_alo[MTOT * DD];
__device__ __nv_bfloat16 g_wqhi[DD * DD];
__device__ __nv_bfloat16 g_wqlo[DD * DD];
__device__ __nv_bfloat16 g_wkhi[DD * DD];
__device__ __nv_bfloat16 g_wklo[DD * DD];
__device__ __nv_bfloat16 g_wvhi[DD * DD];
__device__ __nv_bfloat16 g_wvlo[DD * DD];
__device__ __nv_bfloat16 g_wohi[DD * DD];
__device__ __nv_bfloat16 g_wolo[DD * DD];

// ---------------- helpers ----------------
__device__ __forceinline__ uint32_t smem_u32(const void* p) {
    uint32_t a;
    asm("{ .reg .u64 t; cvta.to.shared.u64 t, %1; cvt.u32.u64 %0, t; }" : "=r"(a) : "l"(p));
    return a;
}
#define CP_ASYNC16(dst, src) \
    asm volatile("cp.async.cg.shared.global [%0], [%1], 16;" :: "r"(dst), "l"(src))
#define CP_COMMIT() asm volatile("cp.async.commit_group;" ::: "memory")
#define CP_WAIT1()  asm volatile("cp.async.wait_group 1;" ::: "memory")
#define CP_WAIT0()  asm volatile("cp.async.wait_group 0;" ::: "memory")

__device__ __forceinline__ void ldsm_x4(uint32_t& r0, uint32_t& r1, uint32_t& r2,
                                        uint32_t& r3, uint32_t addr) {
    asm volatile("ldmatrix.sync.aligned.m8n8.x4.shared.b16 {%0,%1,%2,%3}, [%4];"
                 : "=r"(r0), "=r"(r1), "=r"(r2), "=r"(r3) : "r"(addr));
}
__device__ __forceinline__ void ldsm_x4_t(uint32_t& r0, uint32_t& r1, uint32_t& r2,
                                          uint32_t& r3, uint32_t addr) {
    asm volatile("ldmatrix.sync.aligned.m8n8.x4.trans.shared.b16 {%0,%1,%2,%3}, [%4];"
                 : "=r"(r0), "=r"(r1), "=r"(r2), "=r"(r3) : "r"(addr));
}
__device__ __forceinline__ void mma_bf16(float* d, const uint32_t* a, const uint32_t* b) {
    asm volatile(
        "mma.sync.aligned.m16n8k16.row.col.f32.bf16.bf16.f32 "
        "{%0,%1,%2,%3}, {%4,%5,%6,%7}, {%8,%9}, {%0,%1,%2,%3};"
        : "+f"(d[0]), "+f"(d[1]), "+f"(d[2]), "+f"(d[3])
        : "r"(a[0]), "r"(a[1]), "r"(a[2]), "r"(a[3]), "r"(b[0]), "r"(b[1]));
}

// split x,y (fp32) into packed bf16x2 hi and lo words (elem x in low half)
__device__ __forceinline__ void split_pack(float x, float y, uint32_t& hi, uint32_t& lo) {
    __nv_bfloat16 hx = __float2bfloat16(x);
    __nv_bfloat16 hy = __float2bfloat16(y);
    __nv_bfloat16 lx = __float2bfloat16(x - __bfloat162float(hx));
    __nv_bfloat16 ly = __float2bfloat16(y - __bfloat162float(hy));
    hi = ((uint32_t)__bfloat16_as_ushort(hy) << 16) | (uint32_t)__bfloat16_as_ushort(hx);
    lo = ((uint32_t)__bfloat16_as_ushort(ly) << 16) | (uint32_t)__bfloat16_as_ushort(lx);
}

// ---------------- fp32 -> bf16 hi/lo split kernels ----------------
struct alignas(8) bfq { __nv_bfloat16 a, b, c, d; };

__device__ __forceinline__ void split_one(const float* x, __nv_bfloat16* hi,
                                          __nv_bfloat16* lo, int i) {
    float4 v = *reinterpret_cast<const float4*>(x + i * 4);
    __nv_bfloat16 h0 = __float2bfloat16(v.x);
    __nv_bfloat16 h1 = __float2bfloat16(v.y);
    __nv_bfloat16 h2 = __float2bfloat16(v.z);
    __nv_bfloat16 h3 = __float2bfloat16(v.w);
    bfq hq = {h0, h1, h2, h3};
    bfq lq = {__float2bfloat16(v.x - __bfloat162float(h0)),
              __float2bfloat16(v.y - __bfloat162float(h1)),
              __float2bfloat16(v.z - __bfloat162float(h2)),
              __float2bfloat16(v.w - __bfloat162float(h3))};
    *reinterpret_cast<bfq*>(hi + i * 4) = hq;
    *reinterpret_cast<bfq*>(lo + i * 4) = lq;
}

__global__ __launch_bounds__(256) void split_bf16(
    const float* __restrict__ x, __nv_bfloat16* __restrict__ hi,
    __nv_bfloat16* __restrict__ lo, int n4)
{
    int i = blockIdx.x * blockDim.x + threadIdx.x;
    if (i < n4) split_one(x, hi, lo, i);
}

__global__ __launch_bounds__(256) void split_w4(
    const float* __restrict__ w0, const float* __restrict__ w1,
    const float* __restrict__ w2, const float* __restrict__ w3,
    __nv_bfloat16* __restrict__ h0, __nv_bfloat16* __restrict__ l0,
    __nv_bfloat16* __restrict__ h1, __nv_bfloat16* __restrict__ l1,
    __nv_bfloat16* __restrict__ h2, __nv_bfloat16* __restrict__ l2,
    __nv_bfloat16* __restrict__ h3, __nv_bfloat16* __restrict__ l3)
{
    int w = blockIdx.x >> 10;
    int i = ((blockIdx.x & 1023) << 8) + threadIdx.x;
    const float* x = (w == 0) ? w0 : (w == 1) ? w1 : (w == 2) ? w2 : w3;
    __nv_bfloat16* hi = (w == 0) ? h0 : (w == 1) ? h1 : (w == 2) ? h2 : h3;
    __nv_bfloat16* lo = (w == 0) ? l0 : (w == 1) ? l1 : (w == 2) ? l2 : l3;
    split_one(x, hi, lo, i);
}

// ---------------- HMMA GEMM, bf16x3 split ----------------
#define BK      32
#define LDS_S   40
#define TILE_B  (128 * LDS_S * 2)
#define STAGE_B (4 * TILE_B)
#define GSMEM_TOTAL (2 * STAGE_B)
#define NCHUNK  32

template <int OM>
__global__ __launch_bounds__(256, 2) void gemm3(
    const __nv_bfloat16* __restrict__ Ahi, const __nv_bfloat16* __restrict__ Alo,
    const __nv_bfloat16* __restrict__ W0h, const __nv_bfloat16* __restrict__ W0l,
    const __nv_bfloat16* __restrict__ W1h, const __nv_bfloat16* __restrict__ W1l,
    const __nv_bfloat16* __restrict__ W2h, const __nv_bfloat16* __restrict__ W2l,
    const float* __restrict__ b0, const float* __restrict__ b1, const float* __restrict__ b2,
    float* __restrict__ C0,
    __nv_bfloat16* __restrict__ H0, __nv_bfloat16* __restrict__ L0,
    __nv_bfloat16* __restrict__ H1, __nv_bfloat16* __restrict__ L1,
    __nv_bfloat16* __restrict__ H2, __nv_bfloat16* __restrict__ L2,
    float scale0)
{
    extern __shared__ __align__(16) char smem[];

    const int z = blockIdx.z;
    const __nv_bfloat16* Bh = (z == 0) ? W0h : (z == 1) ? W1h : W2h;
    const __nv_bfloat16* Bl = (z == 0) ? W0l : (z == 1) ? W1l : W2l;
    const float* bias = (z == 0) ? b0 : (z == 1) ? b1 : b2;
    __nv_bfloat16* OH = (z == 0) ? H0 : (z == 1) ? H1 : H2;
    __nv_bfloat16* OL = (z == 0) ? L0 : (z == 1) ? L1 : L2;
    const float scale = (z == 0) ? scale0 : 1.0f;

    const int tid  = threadIdx.x;
    const int wid  = tid >> 5;
    const int lane = tid & 31;
    const int n0   = blockIdx.x * 128;
    const int m0   = blockIdx.y * 128;
    const int wm   = (wid >> 2) * 64;
    const int wn   = (wid & 3) * 32;

    float acc[4][4][4];
#pragma unroll
    for (int i = 0; i < 4; i++)
#pragma unroll
        for (int j = 0; j < 4; j++)
#pragma unroll
            for (int r = 0; r < 4; r++) acc[i][j][r] = 0.f;

    const int ar = (lane & 7) + ((lane >> 3) & 1) * 8;
    const int ac = (lane >> 4) * 8;
    const int br = (lane & 7) + ((lane >> 4) & 1) * 8;
    const int bc = ((lane >> 3) & 1) * 8;

    const uint32_t sbase = smem_u32(smem);
    const int lrow = tid >> 2;
    const int lseg = (tid & 3) * 8;
    auto load_chunk = [&](int c, int s) {
        const int kc = c * BK;
        const uint32_t sb = sbase + s * STAGE_B;
        const __nv_bfloat16* srcs[4] = { Ahi, Alo, Bh, Bl };
        const int rowbase[4] = { m0, m0, n0, n0 };
#pragma unroll
        for (int t4 = 0; t4 < 4; t4++) {
            const __nv_bfloat16* src = srcs[t4];
#pragma unroll
            for (int i = 0; i < 2; i++) {
                int row = lrow + i * 64;
                uint32_t d = sb + t4 * TILE_B + (row * LDS_S + lseg) * 2;
                CP_ASYNC16(d, src + (size_t)(rowbase[t4] + row) * DD + kc + lseg);
            }
        }
        CP_COMMIT();
    };

    load_chunk(0, 0);

    for (int c = 0; c < NCHUNK; c++) {
        const int s = c & 1;
        if (c + 1 < NCHUNK) { load_chunk(c + 1, s ^ 1); CP_WAIT1(); }
        else                { CP_WAIT0(); }
        __syncthreads();

        const uint32_t sb = sbase + s * STAGE_B;
#pragma unroll
        for (int ks = 0; ks < 2; ks++) {
            const int k = ks * 16;
            uint32_t af[4][4];
#pragma unroll
            for (int mi = 0; mi < 4; mi++) {
                uint32_t a = sb + 0 * TILE_B + ((wm + mi * 16 + ar) * LDS_S + k + ac) * 2;
                ldsm_x4(af[mi][0], af[mi][1], af[mi][2], af[mi][3], a);
            }
            uint32_t bfh[4][2];
#pragma unroll
            for (int pr = 0; pr < 2; pr++) {
                uint32_t a = sb + 2 * TILE_B + ((wn + pr * 16 + br) * LDS_S + k + bc) * 2;
                uint32_t r0, r1, r2, r3;
                ldsm_x4(r0, r1, r2, r3, a);
                bfh[pr * 2 + 0][0] = r0; bfh[pr * 2 + 0][1] = r1;
                bfh[pr * 2 + 1][0] = r2; bfh[pr * 2 + 1][1] = r3;
            }
            uint32_t bfl[4][2];
#pragma unroll
            for (int pr = 0; pr < 2; pr++) {
                uint32_t a = sb + 3 * TILE_B + ((wn + pr * 16 + br) * LDS_S + k + bc) * 2;
                uint32_t r0, r1, r2, r3;
                ldsm_x4(r0, r1, r2, r3, a);
                bfl[pr * 2 + 0][0] = r0; bfl[pr * 2 + 0][1] = r1;
                bfl[pr * 2 + 1][0] = r2; bfl[pr * 2 + 1][1] = r3;
            }
#pragma unroll
            for (int mi = 0; mi < 4; mi++)
#pragma unroll
                for (int ni = 0; ni < 4; ni++)
                    mma_bf16(acc[mi][ni], af[mi], bfh[ni]);
#pragma unroll
            for (int mi = 0; mi < 4; mi++)
#pragma unroll
                for (int ni = 0; ni < 4; ni++)
                    mma_bf16(acc[mi][ni], af[mi], bfl[ni]);
#pragma unroll
            for (int mi = 0; mi < 4; mi++) {
                uint32_t a = sb + 1 * TILE_B + ((wm + mi * 16 + ar) * LDS_S + k + ac) * 2;
                ldsm_x4(af[mi][0], af[mi][1], af[mi][2], af[mi][3], a);
            }
#pragma unroll
            for (int mi = 0; mi < 4; mi++)
#pragma unroll
                for (int ni = 0; ni < 4; ni++)
                    mma_bf16(acc[mi][ni], af[mi], bfh[ni]);
        }
        __syncthreads();
    }

    const int t4 = lane >> 2;
    const int t2 = (lane & 3) * 2;
#pragma unroll
    for (int mi = 0; mi < 4; mi++) {
#pragma unroll
        for (int half = 0; half < 2; half++) {
            const int row = m0 + wm + mi * 16 + t4 + half * 8;
#pragma unroll
            for (int ni = 0; ni < 4; ni++) {
                const int col = wn + ni * 8 + t2;
                float ox = (acc[mi][ni][half * 2 + 0] + bias[n0 + col + 0]) * scale;
                float oy = (acc[mi][ni][half * 2 + 1] + bias[n0 + col + 1]) * scale;
                if (OM == 0) {
                    float2 o = make_float2(ox, oy);
                    *reinterpret_cast<float2*>(C0 + (size_t)row * DD + n0 + col) = o;
                } else {
                    uint32_t ph, pl;
                    split_pack(ox, oy, ph, pl);
                    *reinterpret_cast<uint32_t*>(OH + (size_t)row * DD + n0 + col) = ph;
                    *reinterpret_cast<uint32_t*>(OL + (size_t)row * DD + n0 + col) = pl;
                }
            }
        }
    }
}

// ---------------- tensor-core causal flash attention ----------------
// CTA: 64 queries, 4 warps. SINGLE K/V stage (55 KB smem) -> 4 CTAs/SM,
// 16 warps/SM: cross-CTA overlap hides the exposed per-stage load latency.
#define ATT_STR 72                        // halves per smem row (64 + 8)
#define ATT_TILE (64 * ATT_STR * 2)       // 9216 bytes
#define ATT_SMEM (6 * ATT_TILE)           // Qh,Ql + (Kh,Kl,Vh,Vl) = 55296 B

__global__ __launch_bounds__(128) void attn_tc(
    const __nv_bfloat16* __restrict__ Qh, const __nv_bfloat16* __restrict__ Ql,
    const __nv_bfloat16* __restrict__ Kh, const __nv_bfloat16* __restrict__ Kl,
    const __nv_bfloat16* __restrict__ Vh, const __nv_bfloat16* __restrict__ Vl,
    __nv_bfloat16* __restrict__ Ah, __nv_bfloat16* __restrict__ Al)
{
    extern __shared__ __align__(16) char smem[];
    const int qb = blockIdx.x;
    const int b  = blockIdx.y >> 4;
    const int h  = blockIdx.y & 15;
    const int tid = threadIdx.x, wid = tid >> 5, lane = tid & 31;

    const size_t base = ((size_t)b * SS) * DD + (size_t)h * HD;
    const uint32_t sb = smem_u32(smem);
    const uint32_t sQh = sb, sQl = sb + ATT_TILE;
    auto stile = [&](int t) { return sb + (2 + t) * ATT_TILE; };

    // cp.async loader: one 64x64 bf16 tile; 128 threads x 4 chunks of 16B
    const int lr = tid >> 3;           // rows lr, lr+16, lr+32, lr+48
    const int lg = (tid & 7) * 8;      // halves
    auto load_tile = [&](const __nv_bfloat16* src, int row0, uint32_t dst) {
#pragma unroll
        for (int i = 0; i < 4; i++) {
            int row = lr + i * 16;
            CP_ASYNC16(dst + (row * ATT_STR + lg) * 2,
                       src + base + (size_t)(row0 + row) * DD + lg);
        }
    };
    auto load_stage = [&](int kb) {
        const int r0 = kb * 64;
        load_tile(Kh, r0, stile(0));
        load_tile(Kl, r0, stile(1));
        load_tile(Vh, r0, stile(2));
        load_tile(Vl, r0, stile(3));
        CP_COMMIT();
    };

    // stage Q + stage0 K/V
    load_tile(Qh, qb * 64, sQh);
    load_tile(Ql, qb * 64, sQl);
    load_stage(0);
    CP_WAIT0();
    __syncthreads();

    // ldmatrix lane offsets
    const int ar = (lane & 7) + ((lane >> 3) & 1) * 8;
    const int ac = (lane >> 4) * 8;
    const int br = (lane & 7) + ((lane >> 4) & 1) * 8;
    const int bc = ((lane >> 3) & 1) * 8;

    // Q frags (held in regs for the whole kernel)
    uint32_t qh[4][4], ql[4][4];
#pragma unroll
    for (int kt = 0; kt < 4; kt++) {
        uint32_t a = ((wid * 16 + ar) * ATT_STR + kt * 16 + ac) * 2;
        ldsm_x4(qh[kt][0], qh[kt][1], qh[kt][2], qh[kt][3], sQh + a);
        ldsm_x4(ql[kt][0], ql[kt][1], ql[kt][2], ql[kt][3], sQl + a);
    }

    float oacc[8][4];
#pragma unroll
    for (int nt = 0; nt < 8; nt++)
#pragma unroll
        for (int j = 0; j < 4; j++) oacc[nt][j] = 0.f;
    float mrow[2] = { -1e30f, -1e30f };
    float lrow[2] = { 0.f, 0.f };

    const int r0l = lane >> 2;
    const int c0l = (lane & 3) * 2;

    for (int kb = 0; kb <= qb; kb++) {
        // ---- scores S (16x64 per warp), 3-pass split ----
        float sacc[8][4];
#pragma unroll
        for (int nt = 0; nt < 8; nt++)
#pragma unroll
            for (int j = 0; j < 4; j++) sacc[nt][j] = 0.f;

#pragma unroll
        for (int kt = 0; kt < 4; kt++) {
#pragma unroll
            for (int pr = 0; pr < 4; pr++) {
                uint32_t addr = ((pr * 16 + br) * ATT_STR + kt * 16 + bc) * 2;
                uint32_t h0, h1, h2, h3;
                ldsm_x4(h0, h1, h2, h3, stile(0) + addr);   // K_hi
                uint32_t bh0[2] = { h0, h1 }, bh1[2] = { h2, h3 };
                mma_bf16(sacc[pr * 2 + 0], qh[kt], bh0);
                mma_bf16(sacc[pr * 2 + 1], qh[kt], bh1);
                mma_bf16(sacc[pr * 2 + 0], ql[kt], bh0);
                mma_bf16(sacc[pr * 2 + 1], ql[kt], bh1);
                uint32_t l0, l1, l2, l3;
                ldsm_x4(l0, l1, l2, l3, stile(1) + addr);   // K_lo
                uint32_t bl0[2] = { l0, l1 }, bl1[2] = { l2, l3 };
                mma_bf16(sacc[pr * 2 + 0], qh[kt], bl0);
                mma_bf16(sacc[pr * 2 + 1], qh[kt], bl1);
            }
        }

        // ---- causal mask on diagonal block ----
        if (kb == qb) {
            const int rowa = wid * 16 + r0l;
#pragma unroll
            for (int nt = 0; nt < 8; nt++) {
                const int col = nt * 8 + c0l;
                if (col > rowa)          sacc[nt][0] = -3.0e38f;
                if (col + 1 > rowa)      sacc[nt][1] = -3.0e38f;
                if (col > rowa + 8)      sacc[nt][2] = -3.0e38f;
                if (col + 1 > rowa + 8)  sacc[nt][3] = -3.0e38f;
            }
        }

        // ---- online softmax ----
        float mx0 = sacc[0][0], mx1 = sacc[0][2];
#pragma unroll
        for (int nt = 0; nt < 8; nt++) {
            mx0 = fmaxf(mx0, fmaxf(sacc[nt][0], sacc[nt][1]));
            mx1 = fmaxf(mx1, fmaxf(sacc[nt][2], sacc[nt][3]));
        }
        mx0 = fmaxf(mx0, __shfl_xor_sync(0xffffffffu, mx0, 1));
        mx0 = fmaxf(mx0, __shfl_xor_sync(0xffffffffu, mx0, 2));
        mx1 = fmaxf(mx1, __shfl_xor_sync(0xffffffffu, mx1, 1));
        mx1 = fmaxf(mx1, __shfl_xor_sync(0xffffffffu, mx1, 2));
        const float mn0 = fmaxf(mrow[0], mx0);
        const float mn1 = fmaxf(mrow[1], mx1);
        const float cr0 = __expf(mrow[0] - mn0);
        const float cr1 = __expf(mrow[1] - mn1);
        mrow[0] = mn0; mrow[1] = mn1;
        lrow[0] *= cr0; lrow[1] *= cr1;
#pragma unroll
        for (int nt = 0; nt < 8; nt++) {
            oacc[nt][0] *= cr0; oacc[nt][1] *= cr0;
            oacc[nt][2] *= cr1; oacc[nt][3] *= cr1;
        }
        float ls0 = 0.f, ls1 = 0.f;
#pragma unroll
        for (int nt = 0; nt < 8; nt++) {
            float p0 = __expf(sacc[nt][0] - mn0);
            float p1 = __expf(sacc[nt][1] - mn0);
            float p2 = __expf(sacc[nt][2] - mn1);
            float p3 = __expf(sacc[nt][3] - mn1);
            ls0 += p0 + p1; ls1 += p2 + p3;
            sacc[nt][0] = p0; sacc[nt][1] = p1;
            sacc[nt][2] = p2; sacc[nt][3] = p3;
        }
        lrow[0] += ls0; lrow[1] += ls1;

        // ---- P frags (A operand), split hi/lo ----
        uint32_t phi[4][4], plo[4][4];
#pragma unroll
        for (int kt = 0; kt < 4; kt++) {
            split_pack(sacc[2 * kt][0],     sacc[2 * kt][1],     phi[kt][0], plo[kt][0]);
            split_pack(sacc[2 * kt][2],     sacc[2 * kt][3],     phi[kt][1], plo[kt][1]);
            split_pack(sacc[2 * kt + 1][0], sacc[2 * kt + 1][1], phi[kt][2], plo[kt][2]);
            split_pack(sacc[2 * kt + 1][2], sacc[2 * kt + 1][3], phi[kt][3], plo[kt][3]);
        }

        // ---- O += P.V, 3-pass split (V via ldmatrix.trans) ----
#pragma unroll
        for (int kt = 0; kt < 4; kt++) {
#pragma unroll
            for (int pn = 0; pn < 4; pn++) {
                uint32_t addr = ((kt * 16 + (lane & 15)) * ATT_STR
                                 + pn * 16 + ((lane >> 4) << 3)) * 2;
                uint32_t h0, h1, h2, h3;
                ldsm_x4_t(h0, h1, h2, h3, stile(2) + addr);   // V_hi
                uint32_t vh0[2] = { h0, h1 }, vh1[2] = { h2, h3 };
                mma_bf16(oacc[pn * 2 + 0], phi[kt], vh0);
                mma_bf16(oacc[pn * 2 + 1], phi[kt], vh1);
                mma_bf16(oacc[pn * 2 + 0], plo[kt], vh0);
                mma_bf16(oacc[pn * 2 + 1], plo[kt], vh1);
                uint32_t l0, l1, l2, l3;
                ldsm_x4_t(l0, l1, l2, l3, stile(3) + addr);   // V_lo
                uint32_t vl0[2] = { l0, l1 }, vl1[2] = { l2, l3 };
                mma_bf16(oacc[pn * 2 + 0], phi[kt], vl0);
                mma_bf16(oacc[pn * 2 + 1], phi[kt], vl1);
            }
        }

        // next stage: wait for all reads of this stage, then reload in place
        if (kb < qb) {
            __syncthreads();
            load_stage(kb + 1);
            CP_WAIT0();
            __syncthreads();
        }
    }

    // final: reduce l across the 4 lanes of each row, normalize, split, store
    float lt0 = lrow[0], lt1 = lrow[1];
    lt0 += __shfl_xor_sync(0xffffffffu, lt0, 1);
    lt0 += __shfl_xor_sync(0xffffffffu, lt0, 2);
    lt1 += __shfl_xor_sync(0xffffffffu, lt1, 1);
    lt1 += __shfl_xor_sync(0xffffffffu, lt1, 2);
    const float inv0 = 1.f / lt0;
    const float inv1 = 1.f / lt1;

    const int rg0 = b * SS + qb * 64 + wid * 16 + r0l;
    const int rg1 = rg0 + 8;
#pragma unroll
    for (int nt = 0; nt < 8; nt++) {
        const int col = h * HD + nt * 8 + c0l;
        uint32_t ph, pl;
        split_pack(oacc[nt][0] * inv0, oacc[nt][1] * inv0, ph, pl);
        *reinterpret_cast<uint32_t*>(Ah + (size_t)rg0 * DD + col) = ph;
        *reinterpret_cast<uint32_t*>(Al + (size_t)rg0 * DD + col) = pl;
        split_pack(oacc[nt][2] * inv1, oacc[nt][3] * inv1, ph, pl);
        *reinterpret_cast<uint32_t*>(Ah + (size_t)rg1 * DD + col) = ph;
        *reinterpret_cast<uint32_t*>(Al + (size_t)rg1 * DD + col) = pl;
    }
}

// ---------------------------------------------------------------------------
extern "C" void kernel_launch(void* const* d_in, const int* in_sizes, int n_in,
                              void* d_out, int out_size)
{
    const float* X  = (const float*)d_in[0];
    const float* Wq = (const float*)d_in[2];
    const float* bq = (const float*)d_in[3];
    const float* Wk = (const float*)d_in[4];
    const float* bk = (const float*)d_in[5];
    const float* Wv = (const float*)d_in[6];
    const float* bv = (const float*)d_in[7];
    const float* Wo = (const float*)d_in[8];
    const float* bo = (const float*)d_in[9];
    float* out = (float*)d_out;

    __nv_bfloat16 *xhi, *xlo, *qhi, *qlo, *khi, *klo, *vhi, *vlo, *ahi, *alo;
    __nv_bfloat16 *wqhi, *wqlo, *wkhi, *wklo, *wvhi, *wvlo, *wohi, *wolo;
    cudaGetSymbolAddress((void**)&xhi,  g_xhi);  cudaGetSymbolAddress((void**)&xlo,  g_xlo);
    cudaGetSymbolAddress((void**)&qhi,  g_qhi);  cudaGetSymbolAddress((void**)&qlo,  g_qlo);
    cudaGetSymbolAddress((void**)&khi,  g_khi);  cudaGetSymbolAddress((void**)&klo,  g_klo);
    cudaGetSymbolAddress((void**)&vhi,  g_vhi);  cudaGetSymbolAddress((void**)&vlo,  g_vlo);
    cudaGetSymbolAddress((void**)&ahi,  g_ahi);  cudaGetSymbolAddress((void**)&alo,  g_alo);
    cudaGetSymbolAddress((void**)&wqhi, g_wqhi); cudaGetSymbolAddress((void**)&wqlo, g_wqlo);
    cudaGetSymbolAddress((void**)&wkhi, g_wkhi); cudaGetSymbolAddress((void**)&wklo, g_wklo);
    cudaGetSymbolAddress((void**)&wvhi, g_wvhi); cudaGetSymbolAddress((void**)&wvlo, g_wvlo);
    cudaGetSymbolAddress((void**)&wohi, g_wohi); cudaGetSymbolAddress((void**)&wolo, g_wolo);

    cudaFuncSetAttribute(gemm3<0>, cudaFuncAttributeMaxDynamicSharedMemorySize, GSMEM_TOTAL);
    cudaFuncSetAttribute(gemm3<1>, cudaFuncAttributeMaxDynamicSharedMemorySize, GSMEM_TOTAL);
    cudaFuncSetAttribute(attn_tc,  cudaFuncAttributeMaxDynamicSharedMemorySize, ATT_SMEM);

    const int nX4 = MTOT * DD / 4;

    split_bf16<<<nX4 / 256, 256>>>(X, xhi, xlo, nX4);
    split_w4<<<4096, 256>>>(Wq, Wk, Wv, Wo,
                            wqhi, wqlo, wkhi, wklo, wvhi, wvlo, wohi, wolo);

    const dim3 ggrid(DD / 128, MTOT / 128, 3);
    gemm3<1><<<ggrid, 256, GSMEM_TOTAL>>>(xhi, xlo,
                                          wqhi, wqlo, wkhi, wklo, wvhi, wvlo,
                                          bq, bk, bv, nullptr,
                                          qhi, qlo, khi, klo, vhi, vlo, 0.125f);

    attn_tc<<<dim3(SS / 64, BB * HH), 128, ATT_SMEM>>>(qhi, qlo, khi, klo,
                                                       vhi, vlo, ahi, alo);

    const dim3 ogrid(DD / 128, MTOT / 128, 1);
    gemm3<0><<<ogrid, 256, GSMEM_TOTAL>>>(ahi, alo,
                                          wohi, wolo, wohi, wolo, wohi, wolo,
                                          bo, bo, bo, out,
                                          nullptr, nullptr, nullptr, nullptr,
                                          nullptr, nullptr, 1.0f);
}